// round 15
// baseline (speedup 1.0000x reference)
#include <cuda_runtime.h>
#include <cuda_fp16.h>
#include <math.h>
#include <stdint.h>

#define T_TOK 4096
#define D_DIM 1024
#define F_DIM 4096
#define N_EXP 8
#define TOTAL_ROWS (T_TOK * 2)

#define BK 32
#define ROWB 80

// ---- gemm1 geometry (unchanged from R14) ----
#define BM1 128
#define BN1 128
#define APL1 0
#define BPL1 (128 * ROWB)            // 10240
#define STAGE1 (256 * ROWB)          // 20480
#define NBUF 3
#define DSMEM1 (NBUF * STAGE1)       // 61440 (3 CTAs/SM)

// ---- gemm2 geometry: 64x128 CTA, 2 warps of 64x64 ----
#define BM2 64
#define BN2 128
#define APL2 0
#define BPL2 (64 * ROWB)             // 5120
#define STAGE2 (192 * ROWB)          // 15360
#define DSMEM2 (NBUF * STAGE2)       // 46080 (4 CTAs/SM)

// ---- scratch (device globals: no allocations allowed) ----
__device__ __half g_Hh[(size_t)TOTAL_ROWS * F_DIM];
__device__ __half g_W1h[(size_t)N_EXP * F_DIM * D_DIM];
__device__ __half g_W2h[(size_t)N_EXP * D_DIM * F_DIM];
__device__ __half g_xh[(size_t)T_TOK * D_DIM];
__device__ int   g_rowmap[TOTAL_ROWS];
__device__ float g_roww[TOTAL_ROWS];
__device__ int   g_counts[N_EXP];
__device__ int   g_offsets[N_EXP];
__device__ int   g_tope[T_TOK * 2];
__device__ float g_topw[T_TOK * 2];

// ---------------- PTX helpers ----------------
__device__ __forceinline__ uint32_t smem_u32(const void* p) {
    uint32_t a;
    asm("{ .reg .u64 t; cvta.to.shared.u64 t, %1; cvt.u32.u64 %0, t; }" : "=r"(a) : "l"(p));
    return a;
}
__device__ __forceinline__ void cp16(uint32_t dst, const void* src) {
    asm volatile("cp.async.cg.shared.global [%0], [%1], 16;" :: "r"(dst), "l"(src));
}
#define CP_COMMIT() asm volatile("cp.async.commit_group;" ::: "memory")
#define CP_WAIT(n)  asm volatile("cp.async.wait_group %0;" :: "n"(n) : "memory")
__device__ __forceinline__ void ldsm4(uint32_t& r0, uint32_t& r1, uint32_t& r2, uint32_t& r3,
                                      uint32_t a) {
    asm volatile("ldmatrix.sync.aligned.m8n8.x4.shared.b16 {%0,%1,%2,%3}, [%4];"
                 : "=r"(r0), "=r"(r1), "=r"(r2), "=r"(r3) : "r"(a));
}
__device__ __forceinline__ void mma16816(float* c, uint32_t a0, uint32_t a1,
                                         uint32_t a2, uint32_t a3,
                                         uint32_t b0, uint32_t b1) {
    asm volatile("mma.sync.aligned.m16n8k16.row.col.f32.f16.f16.f32 "
                 "{%0,%1,%2,%3}, {%4,%5,%6,%7}, {%8,%9}, {%0,%1,%2,%3};"
                 : "+f"(c[0]), "+f"(c[1]), "+f"(c[2]), "+f"(c[3])
                 : "r"(a0), "r"(a1), "r"(a2), "r"(a3), "r"(b0), "r"(b1));
}

// gemm1 stage (unchanged from R14): warp tile 64x64
__device__ __forceinline__ void compute_stage1(uint32_t bufb, uint32_t aOff,
                                               uint32_t bOffBase, float acc[4][8][4]) {
#pragma unroll
    for (int ks = 0; ks < 2; ks++) {
        uint32_t kb = ks * 32;
        uint32_t b0[8], b1[8];
#pragma unroll
        for (int p = 0; p < 4; p++)
            ldsm4(b0[2 * p], b1[2 * p], b0[2 * p + 1], b1[2 * p + 1],
                  bufb + BPL1 + bOffBase + p * (16 * ROWB) + kb);
#pragma unroll
        for (int mi = 0; mi < 4; mi++) {
            uint32_t a0, a1, a2, a3;
            ldsm4(a0, a1, a2, a3, bufb + APL1 + aOff + mi * (16 * ROWB) + kb);
#pragma unroll
            for (int nj = 0; nj < 8; nj++)
                mma16816(acc[mi][nj], a0, a1, a2, a3, b0[nj], b1[nj]);
        }
    }
}

// gemm2 stage: warp tile 64x64, A-fragment double-buffered across mi
__device__ __forceinline__ void compute_stage2(uint32_t bufb, uint32_t aOff,
                                               uint32_t bOffBase, float acc[4][8][4]) {
#pragma unroll
    for (int ks = 0; ks < 2; ks++) {
        uint32_t kb = ks * 32;
        uint32_t b0[8], b1[8];
#pragma unroll
        for (int p = 0; p < 4; p++)
            ldsm4(b0[2 * p], b1[2 * p], b0[2 * p + 1], b1[2 * p + 1],
                  bufb + BPL2 + bOffBase + p * (16 * ROWB) + kb);
        uint32_t a[2][4];
        ldsm4(a[0][0], a[0][1], a[0][2], a[0][3], bufb + APL2 + aOff + kb);
#pragma unroll
        for (int mi = 0; mi < 4; mi++) {
            if (mi < 3)
                ldsm4(a[(mi + 1) & 1][0], a[(mi + 1) & 1][1],
                      a[(mi + 1) & 1][2], a[(mi + 1) & 1][3],
                      bufb + APL2 + aOff + (mi + 1) * (16 * ROWB) + kb);
            uint32_t* ac = a[mi & 1];
#pragma unroll
            for (int nj = 0; nj < 8; nj++)
                mma16816(acc[mi][nj], ac[0], ac[1], ac[2], ac[3], b0[nj], b1[nj]);
        }
    }
}

// ---------------------------------------------------------------------------
// launch 0: fp32->fp16 converts for W1|W2, zero(out), counts reset
#define X_B4   ((size_t)(T_TOK * D_DIM / 4))          // out float4 count
#define W_B4   ((size_t)N_EXP * F_DIM * D_DIM / 4)
__global__ void f2h_zero_kernel(const float* __restrict__ W1,
                                const float* __restrict__ W2,
                                float* __restrict__ out) {
    size_t i = (size_t)blockIdx.x * blockDim.x + threadIdx.x;
    if (i < X_B4) ((float4*)out)[i] = make_float4(0.f, 0.f, 0.f, 0.f);
    if (i < 8) g_counts[i] = 0;
    const float* s;
    __half* d;
    size_t j = i;
    if (j < W_B4) { s = W1; d = g_W1h; }
    else { s = W2; d = g_W2h; j -= W_B4; }
    float4 v = ((const float4*)s)[j];
    __half2* dp = (__half2*)d;
    dp[2 * j] = __floats2half2_rn(v.x, v.y);
    dp[2 * j + 1] = __floats2half2_rn(v.z, v.w);
}

// launch 1: router (also emits xh)
__global__ void router_kernel(const float* __restrict__ x, const float* __restrict__ Wr) {
    int gtid = blockIdx.x * blockDim.x + threadIdx.x;
    int t = gtid >> 5, lane = gtid & 31;
    if (t >= T_TOK) return;
    const float* xr = x + (size_t)t * D_DIM;
    __half* xhr = g_xh + (size_t)t * D_DIM;
    float xv[32];
#pragma unroll
    for (int i = 0; i < 32; i++) {
        xv[i] = xr[lane + i * 32];
        xhr[lane + i * 32] = __float2half_rn(xv[i]);
    }
    float logit[N_EXP];
#pragma unroll
    for (int e = 0; e < N_EXP; e++) {
        const float* w = Wr + (size_t)e * D_DIM;
        float s = 0.f;
#pragma unroll
        for (int i = 0; i < 32; i++) s += xv[i] * w[lane + i * 32];
#pragma unroll
        for (int o = 16; o > 0; o >>= 1) s += __shfl_xor_sync(0xffffffffu, s, o);
        logit[e] = s;
    }
    if (lane == 0) {
        int i0 = 0; float m0v = logit[0];
#pragma unroll
        for (int e = 1; e < N_EXP; e++) if (logit[e] > m0v) { m0v = logit[e]; i0 = e; }
        int i1 = -1; float m1v = -3.0e38f;
#pragma unroll
        for (int e = 0; e < N_EXP; e++) if (e != i0 && logit[e] > m1v) { m1v = logit[e]; i1 = e; }
        float e1 = expf(m1v - m0v);
        float w0 = 1.f / (1.f + e1);
        float w1 = e1 * w0;
        g_tope[2 * t] = i0;     g_topw[2 * t] = w0;
        g_tope[2 * t + 1] = i1; g_topw[2 * t + 1] = w1;
        atomicAdd(&g_counts[i0], 1);
        atomicAdd(&g_counts[i1], 1);
    }
}

// launch 2: scan + fill merged
__global__ void scanfill_kernel() {
    __shared__ int scur[N_EXP];
    int tid = threadIdx.x;
    if (tid == 0) {
        int o = 0;
        for (int e = 0; e < N_EXP; e++) { g_offsets[e] = o; scur[e] = o; o += g_counts[e]; }
    }
    __syncthreads();
    for (int t = tid; t < T_TOK; t += 256) {
#pragma unroll
        for (int k = 0; k < 2; k++) {
            int e = g_tope[2 * t + k];
            int pos = atomicAdd(&scur[e], 1);
            g_rowmap[pos] = t;
            g_roww[pos] = g_topw[2 * t + k];
        }
    }
}

// ---------------------------------------------------------------------------
// launch 3: GEMM1 (identical to R14): 128x128 CTA, 4 warps 64x64, 3 CTAs/SM
// ---------------------------------------------------------------------------
__global__ __launch_bounds__(128, 3) void gemm1_mma(const float* __restrict__ b1) {
    int e = blockIdx.z;
    int rows = g_counts[e];
    int m0 = blockIdx.y * BM1;
    if (m0 >= rows) return;
    int base = g_offsets[e];
    int n0 = blockIdx.x * BN1;

    extern __shared__ char smem[];
    uint32_t sbase = smem_u32(smem);
    int tid = threadIdx.x;
    int wid = tid >> 5, lane = tid & 31;
    int wm = wid & 1, wn = wid >> 1;
    int g = lane >> 2, q2 = lane & 3;

    int ar = m0 + tid; if (ar >= rows) ar = rows - 1;
    const __half* gpA = g_xh + (size_t)g_rowmap[base + ar] * D_DIM;
    const __half* gpB = g_W1h + ((size_t)e * F_DIM + n0 + tid) * D_DIM;
    uint32_t sdA = sbase + APL1 + tid * ROWB;
    uint32_t sdB = sbase + BPL1 + tid * ROWB;

    int sel = lane >> 3;
    uint32_t aOff = (uint32_t)((wm * 64 + (lane & 15)) * ROWB + (lane >> 4) * 16);
    uint32_t bOffBase = (uint32_t)((wn * 64 + (sel >> 1) * 8 + (lane & 7)) * ROWB + (sel & 1) * 16);

    float acc[4][8][4];
#pragma unroll
    for (int i = 0; i < 4; i++)
#pragma unroll
        for (int j = 0; j < 8; j++)
#pragma unroll
            for (int k = 0; k < 4; k++) acc[i][j][k] = 0.f;

    const int NST = D_DIM / BK;  // 32
#pragma unroll
    for (int s = 0; s < 2; s++) {
        const char* sa = (const char*)gpA + s * 64;
        const char* sb = (const char*)gpB + s * 64;
        uint32_t dA = sdA + s * STAGE1, dB = sdB + s * STAGE1;
#pragma unroll
        for (int i = 0; i < 4; i++) { cp16(dA + 16 * i, sa + 16 * i); cp16(dB + 16 * i, sb + 16 * i); }
        CP_COMMIT();
    }

    int bufC = 0;
    for (int kt = 0; kt < NST; kt++) {
        CP_WAIT(1);
        __syncthreads();
        if (kt + 2 < NST) {
            int s = kt + 2;
            const char* sa = (const char*)gpA + s * 64;
            const char* sb = (const char*)gpB + s * 64;
            int bw = (kt + 2) % NBUF;
            uint32_t dA = sdA + bw * STAGE1, dB = sdB + bw * STAGE1;
#pragma unroll
            for (int i = 0; i < 4; i++) { cp16(dA + 16 * i, sa + 16 * i); cp16(dB + 16 * i, sb + 16 * i); }
        }
        CP_COMMIT();
        compute_stage1(sbase + bufC * STAGE1, aOff, bOffBase, acc);
        bufC = (bufC + 1 == NBUF) ? 0 : bufC + 1;
    }

    const float* bcol = b1 + (size_t)e * F_DIM + n0 + wn * 64;
#pragma unroll
    for (int mi = 0; mi < 4; mi++) {
#pragma unroll
        for (int half_ = 0; half_ < 2; half_++) {
            int gr = m0 + wm * 64 + mi * 16 + g + half_ * 8;
            if (gr < rows) {
                __half* hrow = g_Hh + (size_t)(base + gr) * F_DIM + n0 + wn * 64;
#pragma unroll
                for (int nj = 0; nj < 8; nj++) {
                    int n = nj * 8 + q2 * 2;
                    float v0 = acc[mi][nj][half_ * 2 + 0] + bcol[n];
                    float v1 = acc[mi][nj][half_ * 2 + 1] + bcol[n + 1];
                    float g0 = 0.5f * v0 * (1.0f + erff(v0 * 0.7071067811865475f));
                    float g1 = 0.5f * v1 * (1.0f + erff(v1 * 0.7071067811865475f));
                    *(__half2*)(hrow + n) = __floats2half2_rn(g0, g1);
                }
            }
        }
    }
}

// ---------------------------------------------------------------------------
// launch 4: GEMM2: 64x128 CTA, 2 warps of 64x64, 4 CTAs/SM
// out[tok] += w * (Hh @ W2h^T + b2)  (2-way atomic: deterministic)
// ---------------------------------------------------------------------------
__global__ __launch_bounds__(64, 4) void gemm2_mma(const float* __restrict__ b2,
                                                   float* __restrict__ out) {
    int e = blockIdx.z;
    int rows = g_counts[e];
    int m0 = blockIdx.y * BM2;
    if (m0 >= rows) return;
    int base = g_offsets[e];
    int n0 = blockIdx.x * BN2;   // over D_DIM

    extern __shared__ char smem[];
    uint32_t sbase = smem_u32(smem);
    int tid = threadIdx.x;
    int wid = tid >> 5, lane = tid & 31;
    int wn = wid;                 // 2 warps over N, both cover all 64 M rows
    int g = lane >> 2, q2 = lane & 3;

    // producers: 64 threads: 1 A row + 2 B rows each
    int ar = m0 + tid; if (ar >= rows) ar = rows - 1;
    const __half* gpA = g_Hh + (size_t)(base + ar) * F_DIM;
    const __half* gpB0 = g_W2h + ((size_t)e * D_DIM + n0 + tid) * F_DIM;
    const __half* gpB1 = g_W2h + ((size_t)e * D_DIM + n0 + 64 + tid) * F_DIM;
    uint32_t sdA = sbase + APL2 + tid * ROWB;
    uint32_t sdB0 = sbase + BPL2 + tid * ROWB;
    uint32_t sdB1 = sbase + BPL2 + (64 + tid) * ROWB;

    int sel = lane >> 3;
    uint32_t aOff = (uint32_t)((lane & 15) * ROWB + (lane >> 4) * 16);
    uint32_t bOffBase = (uint32_t)((wn * 64 + (sel >> 1) * 8 + (lane & 7)) * ROWB + (sel & 1) * 16);

    float acc[4][8][4];
#pragma unroll
    for (int i = 0; i < 4; i++)
#pragma unroll
        for (int j = 0; j < 8; j++)
#pragma unroll
            for (int k = 0; k < 4; k++) acc[i][j][k] = 0.f;

    const int NST = F_DIM / BK;  // 128
#pragma unroll
    for (int s = 0; s < 2; s++) {
        const char* sa = (const char*)gpA + s * 64;
        const char* sb0 = (const char*)gpB0 + s * 64;
        const char* sb1 = (const char*)gpB1 + s * 64;
        uint32_t dA = sdA + s * STAGE2, dB0 = sdB0 + s * STAGE2, dB1 = sdB1 + s * STAGE2;
#pragma unroll
        for (int i = 0; i < 4; i++) {
            cp16(dA + 16 * i, sa + 16 * i);
            cp16(dB0 + 16 * i, sb0 + 16 * i);
            cp16(dB1 + 16 * i, sb1 + 16 * i);
        }
        CP_COMMIT();
    }

    int bufC = 0;
    for (int kt = 0; kt < NST; kt++) {
        CP_WAIT(1);
        __syncthreads();
        if (kt + 2 < NST) {
            int s = kt + 2;
            const char* sa = (const char*)gpA + s * 64;
            const char* sb0 = (const char*)gpB0 + s * 64;
            const char* sb1 = (const char*)gpB1 + s * 64;
            int bw = (kt + 2) % NBUF;
            uint32_t dA = sdA + bw * STAGE2, dB0 = sdB0 + bw * STAGE2, dB1 = sdB1 + bw * STAGE2;
#pragma unroll
            for (int i = 0; i < 4; i++) {
                cp16(dA + 16 * i, sa + 16 * i);
                cp16(dB0 + 16 * i, sb0 + 16 * i);
                cp16(dB1 + 16 * i, sb1 + 16 * i);
            }
        }
        CP_COMMIT();
        compute_stage2(sbase + bufC * STAGE2, aOff, bOffBase, acc);
        bufC = (bufC + 1 == NBUF) ? 0 : bufC + 1;
    }

    const float* bcol = b2 + (size_t)e * D_DIM + n0 + wn * 64;
#pragma unroll
    for (int mi = 0; mi < 4; mi++) {
#pragma unroll
        for (int half_ = 0; half_ < 2; half_++) {
            int gr = m0 + mi * 16 + g + half_ * 8;
            if (gr < rows) {
                int tok = g_rowmap[base + gr];
                float w = g_roww[base + gr];
                float* op = out + (size_t)tok * D_DIM + n0 + wn * 64;
#pragma unroll
                for (int nj = 0; nj < 8; nj++) {
                    int n = nj * 8 + q2 * 2;
                    float v0 = acc[mi][nj][half_ * 2 + 0] + bcol[n];
                    float v1 = acc[mi][nj][half_ * 2 + 1] + bcol[n + 1];
                    atomicAdd(&op[n], w * v0);
                    atomicAdd(&op[n + 1], w * v1);
                }
            }
        }
    }
}

// ---------------------------------------------------------------------------
extern "C" void kernel_launch(void* const* d_in, const int* in_sizes, int n_in,
                              void* d_out, int out_size) {
    const float* x  = (const float*)d_in[0];
    const float* Wr = (const float*)d_in[1];
    const float* W1 = (const float*)d_in[2];
    const float* b1 = (const float*)d_in[3];
    const float* W2 = (const float*)d_in[4];
    const float* b2 = (const float*)d_in[5];
    float* out = (float*)d_out;

    cudaFuncSetAttribute(gemm1_mma, cudaFuncAttributeMaxDynamicSharedMemorySize, DSMEM1);
    cudaFuncSetAttribute(gemm2_mma, cudaFuncAttributeMaxDynamicSharedMemorySize, DSMEM2);

    // launch indices: 0 f2h_zero, 1 router, 2 scanfill, 3 gemm1 (ncu target), 4 gemm2
    f2h_zero_kernel<<<(unsigned)((2 * W_B4) / 256), 256>>>(W1, W2, out);
    router_kernel<<<(T_TOK * 32) / 256, 256>>>(x, Wr);
    scanfill_kernel<<<1, 256>>>();
    gemm1_mma<<<dim3(F_DIM / BN1, T_TOK / BM1, N_EXP), 128, DSMEM1>>>(b1);
    gemm2_mma<<<dim3(D_DIM / BN2, T_TOK / BM2, N_EXP), 64, DSMEM2>>>(b2, out);
}